// round 14
// baseline (speedup 1.0000x reference)
#include <cuda_runtime.h>
#include <cuda_fp16.h>
#include <stdint.h>

#define NN_MAX 50000
#define NE_MAX 800000
#define GRID 148          // 1 CTA per SM — all co-resident

// ---------------- device scratch ----------------
__device__ float g_flow_in[NN_MAX * 64];
__device__ float g_flow_out[NN_MAX * 64];
__device__ int4  g_elist0[NE_MAX];   // (eid, col, row, 0) for row<col
__device__ int4  g_elist1[NE_MAX];   // (eid, col, row, 0) for row>col
__device__ int   g_counts[2];        // contract: 0 at kernel entry and exit
__device__ unsigned g_cnt[2];        // monotonic barrier counters (never reset)

// ---------------- smem layout (bytes) ----------------
#define OFF_W1   0        // 128n x 128k fp16   32KB
#define OFF_W2   32768    // 64n x 128k fp16    16KB
#define OFF_A0   49152    // A buffer 0 (256 rows)  64KB
#define OFF_A1   114688   // A buffer 1 (256 rows)  64KB
#define OFF_B1   180224   // 128 f32
#define OFF_B2   180736   // 64 f32
#define OFF_IDX0 180992   // 256 int
#define OFF_IDX1 182016   // 256 int
#define SMEM_TOTAL 183040

#define SWZ(row, cb) ((uint32_t)(row) * 256u + (((uint32_t)(cb)) ^ ((((uint32_t)(row)) & 7u) << 4)))

__device__ __forceinline__ uint32_t smem_u32(const void* p) {
    uint32_t a;
    asm("{ .reg .u64 t; cvta.to.shared.u64 t, %1; cvt.u32.u64 %0, t; }" : "=r"(a) : "l"(p));
    return a;
}

#define LDMX4(r, a) \
    asm volatile("ldmatrix.sync.aligned.m8n8.x4.shared.b16 {%0,%1,%2,%3}, [%4];" \
        : "=r"((r)[0]), "=r"((r)[1]), "=r"((r)[2]), "=r"((r)[3]) : "r"(a))
#define MMA16816(c, a, b0, b1) \
    asm volatile("mma.sync.aligned.m16n8k16.row.col.f32.f16.f16.f32 " \
        "{%0,%1,%2,%3}, {%4,%5,%6,%7}, {%8,%9}, {%0,%1,%2,%3};" \
        : "+f"((c)[0]), "+f"((c)[1]), "+f"((c)[2]), "+f"((c)[3]) \
        : "r"((a)[0]), "r"((a)[1]), "r"((a)[2]), "r"((a)[3]), "r"(b0), "r"(b1))

// ---------------- device-wide monotonic barrier ----------------
__device__ __forceinline__ void grid_barrier(int i) {
    __syncthreads();
    if (threadIdx.x == 0) {
        __threadfence();
        unsigned old = atomicAdd(&g_cnt[i], 1u);
        unsigned target = old - (old % gridDim.x) + gridDim.x;
        while (atomicAdd(&g_cnt[i], 0u) < target) __nanosleep(64);
    }
    __syncthreads();
}

// ---------------- weight staging ----------------
__device__ __forceinline__ void stage_weights(char* S, int tid,
        const float* __restrict__ W1, const float* __restrict__ b1,
        const float* __restrict__ W2, const float* __restrict__ b2) {
    for (int i = tid; i < 128 * 128; i += 256) {
        int n = i >> 7, k = i & 127;
        *(__half*)(S + OFF_W1 + SWZ(n, k * 2)) = __float2half_rn(W1[k * 128 + n]);
    }
    for (int i = tid; i < 64 * 128; i += 256) {
        int n = i >> 7, k = i & 127;
        *(__half*)(S + OFF_W2 + SWZ(n, k * 2)) = __float2half_rn(W2[k * 64 + n]);
    }
    if (tid < 128) ((float*)(S + OFF_B1))[tid] = b1[tid];
    if (tid < 64)  ((float*)(S + OFF_B2))[tid] = b2[tid];
}

__device__ __forceinline__ void cvt_sts(char* S, uint32_t dstoff, int r, int cb, float4 f) {
    __half2 p0 = __floats2half2_rn(f.x, f.y);
    __half2 p1 = __floats2half2_rn(f.z, f.w);
    uint2 v;
    v.x = *(uint32_t*)&p0;
    v.y = *(uint32_t*)&p1;
    *(uint2*)(S + dstoff + SWZ(r, cb)) = v;
}

// ---------------- gather one 256-row chunk into A buffer ----------------
__device__ __forceinline__ void gather_chunk(
    char* S, uint32_t dstoff, uint32_t idxoff,
    int base, int count, int w,
    const int4* __restrict__ elist,
    const float* __restrict__ Ap, const float* __restrict__ Bp,
    const float* __restrict__ x, const float* __restrict__ eattr,
    int wid, int l)
{
    const int g_rsub = l >> 4;
    const int g_half = (l >> 3) & 1;
    const int g_part = l & 7;
    int* sIdx = (int*)(S + idxoff);

    #pragma unroll
    for (int pass = 0; pass < 16; pass++) {
        int r = pass * 16 + (wid << 1) + g_rsub;
        int idx = base + r;
        bool valid = idx < count;
        int aIdx, bIdx, scat;
        if (w < 2) {
            int4 rec = valid ? __ldg(&elist[idx]) : make_int4(0, 0, -1, 0);
            bIdx = rec.x;   // eid  -> eattr
            aIdx = rec.y;   // col  -> x
            scat = rec.z;   // row  -> scatter target
        } else {
            aIdx = idx; bIdx = idx; scat = valid ? idx : -1;
        }
        if ((l & 15) == 0) sIdx[r] = valid ? scat : -1;
        const float4* src;
        if (w < 2)
            src = g_half ? (const float4*)(eattr + (size_t)bIdx * 64)
                         : (const float4*)(x + (size_t)aIdx * 64);
        else
            src = g_half ? (const float4*)(Bp + (size_t)bIdx * 64)
                         : (const float4*)(Ap + (size_t)aIdx * 64);
        #pragma unroll
        for (int j = 0; j < 2; j++) {
            float4 f;
            if (valid)
                f = (w == 2) ? __ldcg(&src[g_part + 8 * j]) : __ldg(&src[g_part + 8 * j]);
            else
                f = make_float4(0.f, 0.f, 0.f, 0.f);
            cvt_sts(S, dstoff, r, g_half * 128 + (g_part + 8 * j) * 8, f);
        }
    }
}

// ---------------- pipelined fused 2-layer MLP, 256-row chunks ----------------
__device__ __forceinline__ void run_mlp(
    char* S, uint32_t sb, int tid, int wid, int l,
    int w, int count, const int4* __restrict__ elist, float* __restrict__ scatp,
    const float* __restrict__ Ap, const float* __restrict__ Bp,
    const float* __restrict__ x, const float* __restrict__ eattr,
    int ctaoff, int cstride, float* __restrict__ nodeout)
{
    const int mg = wid & 3;          // m-group: rows mg*64 .. +63
    const int nh = wid >> 2;         // n-half
    const int mbase = mg * 64;
    const int ccol = (l & 3) * 2;

    const uint32_t a_row  = (uint32_t)(mbase + (l & 15));
    const uint32_t a_cb16 = (uint32_t)((l >> 4) * 16);
    const uint32_t a_xor  = (a_row & 7u) << 4;
    const uint32_t a_lane = a_row * 256u;          // + buffer base per chunk

    const uint32_t b_rowoff = (uint32_t)(((l >> 4) << 3) + (l & 7));
    const uint32_t b_cb16   = ((uint32_t)(l >> 3) & 1u) * 16u;
    const uint32_t b_xor    = ((uint32_t)l & 7u) << 4;
    const uint32_t bW1 = sb + OFF_W1 + ((uint32_t)(nh * 64) + b_rowoff) * 256u;
    const uint32_t bW2 = sb + OFF_W2 + ((uint32_t)(nh * 32) + b_rowoff) * 256u;

    const int erow = (l >> 2);
    const uint32_t e_xor = ((uint32_t)erow & 7u) << 4;

    float bias1[8][2], bias2[4][2];
    {
        const float* B1s = (const float*)(S + OFF_B1);
        const float* B2s = (const float*)(S + OFF_B2);
        #pragma unroll
        for (int nt = 0; nt < 8; nt++) {
            int col = nh * 64 + nt * 8 + ccol;
            bias1[nt][0] = B1s[col];
            bias1[nt][1] = B1s[col + 1];
        }
        #pragma unroll
        for (int nt = 0; nt < 4; nt++) {
            int col = nh * 32 + nt * 8 + ccol;
            bias2[nt][0] = B2s[col];
            bias2[nt][1] = B2s[col + 1];
        }
    }

    int nch = (count + 255) >> 8;
    if (ctaoff >= nch) return;   // uniform per CTA — safe with in-loop syncs

    // ---- prologue: gather first chunk into A0 ----
    gather_chunk(S, OFF_A0, OFF_IDX0, ctaoff << 8, count, w,
                 elist, Ap, Bp, x, eattr, wid, l);
    __syncthreads();

    int p = 0;
    for (int ch = ctaoff; ch < nch; ch += cstride, p ^= 1) {
        const uint32_t bufoff = p ? OFF_A1 : OFF_A0;
        const uint32_t aCur = sb + bufoff + a_lane;
        const uint32_t curIdx = p ? OFF_IDX1 : OFF_IDX0;

        // ---- layer 1: 64m x 64n per warp, K=128, from A[p] ----
        float acc1[4][8][4];
        #pragma unroll
        for (int mt = 0; mt < 4; mt++)
            #pragma unroll
            for (int nt = 0; nt < 8; nt++) {
                acc1[mt][nt][0] = bias1[nt][0];
                acc1[mt][nt][1] = bias1[nt][1];
                acc1[mt][nt][2] = bias1[nt][0];
                acc1[mt][nt][3] = bias1[nt][1];
            }
        #pragma unroll
        for (int kt = 0; kt < 8; kt++) {
            uint32_t ka = (uint32_t)(kt * 32);
            uint32_t af[4][4];
            #pragma unroll
            for (int mt = 0; mt < 4; mt++)
                LDMX4(af[mt], aCur + (uint32_t)(mt * 16) * 256u + ((ka + a_cb16) ^ a_xor));
            #pragma unroll
            for (int np = 0; np < 4; np++) {
                uint32_t bfr[4];
                LDMX4(bfr, bW1 + (uint32_t)(np * 4096) + ((ka + b_cb16) ^ b_xor));
                #pragma unroll
                for (int mt = 0; mt < 4; mt++) {
                    MMA16816(acc1[mt][2*np],   af[mt], bfr[0], bfr[1]);
                    MMA16816(acc1[mt][2*np+1], af[mt], bfr[2], bfr[3]);
                }
            }
        }

        // ---- overlapped: gather next chunk into A[p^1] ----
        int nxt = ch + cstride;
        if (nxt < nch)
            gather_chunk(S, p ? OFF_A0 : OFF_A1, p ? OFF_IDX0 : OFF_IDX1,
                         nxt << 8, count, w, elist, Ap, Bp, x, eattr, wid, l);
        __syncthreads();   // all MMA1 reads of A[p] done before in-place epi1

        // ---- epilogue 1: relu -> fp16, in-place into A[p] ----
        #pragma unroll
        for (int mt = 0; mt < 4; mt++) {
            uint32_t r0 = (uint32_t)(mbase + mt * 16 + erow);
            #pragma unroll
            for (int nt = 0; nt < 8; nt++) {
                uint32_t cb = (uint32_t)((nh * 64 + nt * 8 + ccol) * 2);
                __half2 h0 = __floats2half2_rn(fmaxf(acc1[mt][nt][0], 0.f), fmaxf(acc1[mt][nt][1], 0.f));
                __half2 h1 = __floats2half2_rn(fmaxf(acc1[mt][nt][2], 0.f), fmaxf(acc1[mt][nt][3], 0.f));
                *(uint32_t*)(S + bufoff + r0 * 256u + (cb ^ e_xor)) = *(uint32_t*)&h0;
                *(uint32_t*)(S + bufoff + (r0 + 8u) * 256u + (cb ^ e_xor)) = *(uint32_t*)&h1;
            }
        }
        __syncthreads();

        // ---- layer 2: 64m x 32n per warp, K=128, from A[p] (=H1) ----
        {
            float acc2[4][4][4];
            #pragma unroll
            for (int mt = 0; mt < 4; mt++)
                #pragma unroll
                for (int nt = 0; nt < 4; nt++) {
                    acc2[mt][nt][0] = bias2[nt][0];
                    acc2[mt][nt][1] = bias2[nt][1];
                    acc2[mt][nt][2] = bias2[nt][0];
                    acc2[mt][nt][3] = bias2[nt][1];
                }
            #pragma unroll
            for (int kt = 0; kt < 8; kt++) {
                uint32_t ka = (uint32_t)(kt * 32);
                uint32_t af[4][4];
                #pragma unroll
                for (int mt = 0; mt < 4; mt++)
                    LDMX4(af[mt], aCur + (uint32_t)(mt * 16) * 256u + ((ka + a_cb16) ^ a_xor));
                #pragma unroll
                for (int np = 0; np < 2; np++) {
                    uint32_t bfr[4];
                    LDMX4(bfr, bW2 + (uint32_t)(np * 4096) + ((ka + b_cb16) ^ b_xor));
                    #pragma unroll
                    for (int mt = 0; mt < 4; mt++) {
                        MMA16816(acc2[mt][2*np],   af[mt], bfr[0], bfr[1]);
                        MMA16816(acc2[mt][2*np+1], af[mt], bfr[2], bfr[3]);
                    }
                }
            }

            // ---- epilogue 2: relu + shuffle-pair into float4 + scatter ----
            int* sIdx = (int*)(S + curIdx);
            const int cbase = nh * 32 + 4 * ((l >> 1) & 1);
            #pragma unroll
            for (int mt = 0; mt < 4; mt++) {
                int r0 = mbase + mt * 16 + erow;
                int myrow = r0 + ((l & 1) << 3);
                int node = sIdx[myrow];
                #pragma unroll
                for (int nt = 0; nt < 4; nt++) {
                    float v0 = fmaxf(acc2[mt][nt][0], 0.f);
                    float v1 = fmaxf(acc2[mt][nt][1], 0.f);
                    float v2 = fmaxf(acc2[mt][nt][2], 0.f);
                    float v3 = fmaxf(acc2[mt][nt][3], 0.f);
                    float s0 = __shfl_xor_sync(0xffffffffu, v0, 1);
                    float s1 = __shfl_xor_sync(0xffffffffu, v1, 1);
                    float s2 = __shfl_xor_sync(0xffffffffu, v2, 1);
                    float s3 = __shfl_xor_sync(0xffffffffu, v3, 1);
                    float4 q = (l & 1) ? make_float4(s2, s3, v2, v3)
                                       : make_float4(v0, v1, s0, s1);
                    if (node >= 0) {
                        int col = cbase + nt * 8;
                        if (w < 2)
                            atomicAdd((float4*)(scatp + (size_t)node * 64 + col), q);
                        else
                            *(float4*)(nodeout + (size_t)node * 64 + col) = q;
                    }
                }
            }
        }
        __syncthreads();   // A[p] consumed; A[p^1] gather STS drained
    }
}

// ---------------- single persistent kernel ----------------
__global__ void __launch_bounds__(256, 1)
fused_kernel(int nN, int nE,
             const float* __restrict__ x, const void* __restrict__ eidx,
             const float* __restrict__ eattr,
             const float* __restrict__ Wo1, const float* __restrict__ bo1,
             const float* __restrict__ Wo2, const float* __restrict__ bo2,
             const float* __restrict__ Wi1, const float* __restrict__ bi1,
             const float* __restrict__ Wi2, const float* __restrict__ bi2,
             const float* __restrict__ Wn1, const float* __restrict__ bn1,
             const float* __restrict__ Wn2, const float* __restrict__ bn2,
             float* __restrict__ nodeout)
{
    extern __shared__ __align__(256) char smem[];
    char* S = smem;
    const uint32_t sb = smem_u32(smem);
    const int tid = threadIdx.x;
    const int wid = tid >> 5;
    const int l = tid & 31;
    const long long* p64 = (const long long*)eidx;
    const int* p32 = (const int*)eidx;

    // per-CTA index-dtype detection
    __shared__ int s_is64;
    if (tid == 0) {
        const int* wds = (const int*)eidx;
        int nz = 0;
        #pragma unroll
        for (int k = 0; k < 32; k++) nz |= wds[2 * k + 1];
        s_is64 = (nz == 0) ? 1 : 0;
    }

    // edge-direction for this CTA; stage edge weights (overlaps phase 0)
    const int w = blockIdx.x & 1;
    stage_weights(S, tid,
                  w ? Wi1 : Wo1, w ? bi1 : bo1,
                  w ? Wi2 : Wo2, w ? bi2 : bo2);
    __syncthreads();
    const int is64 = s_is64;

    // ---- phase 0: zero flows + compaction into packed int4 records ----
    {
        int stride = gridDim.x * 256;
        for (int e0 = blockIdx.x * 256 + wid * 32; e0 < nE; e0 += stride) {
            int e = e0 + l;
            bool is_out = false, is_in = false;
            int r = 0, c = 0;
            if (e < nE) {
                if (is64) { r = (int)p64[e]; c = (int)p64[nE + e]; }
                else      { r = p32[e];      c = p32[nE + e]; }
                is_out = (r < c);
                is_in  = (r > c);
            }
            unsigned mo = __ballot_sync(0xffffffffu, is_out);
            unsigned mi = __ballot_sync(0xffffffffu, is_in);
            int bo = 0, bi = 0;
            if (l == 0) {
                if (mo) bo = atomicAdd(&g_counts[0], __popc(mo));
                if (mi) bi = atomicAdd(&g_counts[1], __popc(mi));
            }
            bo = __shfl_sync(0xffffffffu, bo, 0);
            bi = __shfl_sync(0xffffffffu, bi, 0);
            unsigned lt = (1u << l) - 1u;
            if (is_out) g_elist0[bo + __popc(mo & lt)] = make_int4(e, c, r, 0);
            if (is_in)  g_elist1[bi + __popc(mi & lt)] = make_int4(e, c, r, 0);
        }
        int total = nN * 16;
        float4 z = make_float4(0.f, 0.f, 0.f, 0.f);
        for (int i = blockIdx.x * 256 + tid; i < total; i += gridDim.x * 256) {
            ((float4*)g_flow_in)[i]  = z;
            ((float4*)g_flow_out)[i] = z;
        }
    }
    grid_barrier(0);

    // ---- phase 1: edge MLPs (even CTAs: out-list, odd CTAs: in-list) ----
    {
        int count = g_counts[w];
        const int4* elist = w ? g_elist1 : g_elist0;
        float* scatp = w ? g_flow_in : g_flow_out;
        run_mlp(S, sb, tid, wid, l, w, count, elist, scatp,
                nullptr, nullptr, x, eattr,
                blockIdx.x >> 1, gridDim.x >> 1, nullptr);
    }
    grid_barrier(1);

    // ---- phase 2: node MLP ----
    stage_weights(S, tid, Wn1, bn1, Wn2, bn2);
    __syncthreads();
    run_mlp(S, sb, tid, wid, l, 2, nN, nullptr, nullptr,
            g_flow_in, g_flow_out, x, eattr,
            blockIdx.x, gridDim.x, nodeout);

    // restore g_counts = 0 for the next launch (contract)
    if (blockIdx.x == 0 && tid == 0) {
        g_counts[0] = 0;
        g_counts[1] = 0;
    }
}

// ---------------- launch ----------------
extern "C" void kernel_launch(void* const* d_in, const int* in_sizes, int n_in,
                              void* d_out, int out_size) {
    const float* x     = (const float*)d_in[0];
    const void*  eidx  = d_in[1];
    const float* eattr = (const float*)d_in[2];
    const float* Wo1 = (const float*)d_in[3];
    const float* bo1 = (const float*)d_in[4];
    const float* Wo2 = (const float*)d_in[5];
    const float* bo2 = (const float*)d_in[6];
    const float* Wi1 = (const float*)d_in[7];
    const float* bi1 = (const float*)d_in[8];
    const float* Wi2 = (const float*)d_in[9];
    const float* bi2 = (const float*)d_in[10];
    const float* Wn1 = (const float*)d_in[11];
    const float* bn1 = (const float*)d_in[12];
    const float* Wn2 = (const float*)d_in[13];
    const float* bn2 = (const float*)d_in[14];

    int nN = in_sizes[0] / 64;
    int nE = in_sizes[2] / 64;

    cudaFuncSetAttribute(fused_kernel, cudaFuncAttributeMaxDynamicSharedMemorySize, SMEM_TOTAL);

    fused_kernel<<<GRID, 256, SMEM_TOTAL>>>(nN, nE, x, eidx, eattr,
                                            Wo1, bo1, Wo2, bo2,
                                            Wi1, bi1, Wi2, bi2,
                                            Wn1, bn1, Wn2, bn2,
                                            (float*)d_out);
}

// round 15
// speedup vs baseline: 1.1014x; 1.1014x over previous
#include <cuda_runtime.h>
#include <cuda_fp16.h>
#include <stdint.h>

#define NN_MAX 50000
#define NE_MAX 800000
#define GRID 148          // 1 CTA per SM — all co-resident

// ---------------- device scratch ----------------
__device__ float g_flow_in[NN_MAX * 64];
__device__ float g_flow_out[NN_MAX * 64];
__device__ int4  g_elist0[NE_MAX];   // (eid, col, row, 0) for row<col
__device__ int4  g_elist1[NE_MAX];   // (eid, col, row, 0) for row>col
__device__ int   g_counts[2];        // contract: 0 at kernel entry and exit
__device__ unsigned g_cnt[2];        // monotonic barrier counters (never reset)

// ---------------- smem layout (bytes) ----------------
#define OFF_W1   0        // 128n x 128k fp16   32KB
#define OFF_W2   32768    // 64n x 128k fp16    16KB
#define OFF_A0   49152    // A buffer 0 (128 rows)  32KB
#define OFF_A1   81920    // A buffer 1 (128 rows)  32KB
#define OFF_B1   114688   // 128 f32
#define OFF_B2   115200   // 64 f32
#define OFF_IDX0 115456   // 128 int
#define OFF_IDX1 115968   // 128 int
#define SMEM_TOTAL 116480

#define SWZ(row, cb) ((uint32_t)(row) * 256u + (((uint32_t)(cb)) ^ ((((uint32_t)(row)) & 7u) << 4)))

__device__ __forceinline__ uint32_t smem_u32(const void* p) {
    uint32_t a;
    asm("{ .reg .u64 t; cvta.to.shared.u64 t, %1; cvt.u32.u64 %0, t; }" : "=r"(a) : "l"(p));
    return a;
}

#define LDMX4(r, a) \
    asm volatile("ldmatrix.sync.aligned.m8n8.x4.shared.b16 {%0,%1,%2,%3}, [%4];" \
        : "=r"((r)[0]), "=r"((r)[1]), "=r"((r)[2]), "=r"((r)[3]) : "r"(a))
#define MMA16816(c, a, b0, b1) \
    asm volatile("mma.sync.aligned.m16n8k16.row.col.f32.f16.f16.f32 " \
        "{%0,%1,%2,%3}, {%4,%5,%6,%7}, {%8,%9}, {%0,%1,%2,%3};" \
        : "+f"((c)[0]), "+f"((c)[1]), "+f"((c)[2]), "+f"((c)[3]) \
        : "r"((a)[0]), "r"((a)[1]), "r"((a)[2]), "r"((a)[3]), "r"(b0), "r"(b1))
#define MMA16816R(c, a0, a1, a2, a3, b0, b1) \
    asm volatile("mma.sync.aligned.m16n8k16.row.col.f32.f16.f16.f32 " \
        "{%0,%1,%2,%3}, {%4,%5,%6,%7}, {%8,%9}, {%0,%1,%2,%3};" \
        : "+f"((c)[0]), "+f"((c)[1]), "+f"((c)[2]), "+f"((c)[3]) \
        : "r"(a0), "r"(a1), "r"(a2), "r"(a3), "r"(b0), "r"(b1))

// ---------------- device-wide monotonic barrier ----------------
__device__ __forceinline__ void grid_barrier(int i) {
    __syncthreads();
    if (threadIdx.x == 0) {
        __threadfence();
        unsigned old = atomicAdd(&g_cnt[i], 1u);
        unsigned target = old - (old % gridDim.x) + gridDim.x;
        while (atomicAdd(&g_cnt[i], 0u) < target) __nanosleep(64);
    }
    __syncthreads();
}

// ---------------- weight staging ----------------
__device__ __forceinline__ void stage_weights(char* S, int tid,
        const float* __restrict__ W1, const float* __restrict__ b1,
        const float* __restrict__ W2, const float* __restrict__ b2) {
    for (int i = tid; i < 128 * 128; i += 256) {
        int n = i >> 7, k = i & 127;
        *(__half*)(S + OFF_W1 + SWZ(n, k * 2)) = __float2half_rn(W1[k * 128 + n]);
    }
    for (int i = tid; i < 64 * 128; i += 256) {
        int n = i >> 7, k = i & 127;
        *(__half*)(S + OFF_W2 + SWZ(n, k * 2)) = __float2half_rn(W2[k * 64 + n]);
    }
    if (tid < 128) ((float*)(S + OFF_B1))[tid] = b1[tid];
    if (tid < 64)  ((float*)(S + OFF_B2))[tid] = b2[tid];
}

__device__ __forceinline__ void cvt_sts(char* S, uint32_t dstoff, int r, int cb, float4 f) {
    __half2 p0 = __floats2half2_rn(f.x, f.y);
    __half2 p1 = __floats2half2_rn(f.z, f.w);
    uint2 v;
    v.x = *(uint32_t*)&p0;
    v.y = *(uint32_t*)&p1;
    *(uint2*)(S + dstoff + SWZ(r, cb)) = v;
}

// ---------------- gather one 128-row chunk into A buffer (R11-proven) ----------------
__device__ __forceinline__ void gather_chunk(
    char* S, uint32_t dstoff, uint32_t idxoff,
    int base, int count, int w,
    const int4* __restrict__ elist,
    const float* __restrict__ Ap, const float* __restrict__ Bp,
    const float* __restrict__ x, const float* __restrict__ eattr,
    int wid, int l)
{
    const int g_rsub = l >> 4;
    const int g_half = (l >> 3) & 1;
    const int g_part = l & 7;
    int* sIdx = (int*)(S + idxoff);

    #pragma unroll
    for (int pass = 0; pass < 8; pass++) {
        int r = pass * 16 + (wid << 1) + g_rsub;
        int idx = base + r;
        bool valid = idx < count;
        int aIdx, bIdx, scat;
        if (w < 2) {
            int4 rec = valid ? __ldg(&elist[idx]) : make_int4(0, 0, -1, 0);
            bIdx = rec.x;   // eid  -> eattr
            aIdx = rec.y;   // col  -> x
            scat = rec.z;   // row  -> scatter target
        } else {
            aIdx = idx; bIdx = idx; scat = valid ? idx : -1;
        }
        if ((l & 15) == 0) sIdx[r] = valid ? scat : -1;
        const float4* src;
        if (w < 2)
            src = g_half ? (const float4*)(eattr + (size_t)bIdx * 64)
                         : (const float4*)(x + (size_t)aIdx * 64);
        else
            src = g_half ? (const float4*)(Bp + (size_t)bIdx * 64)
                         : (const float4*)(Ap + (size_t)aIdx * 64);
        #pragma unroll
        for (int j = 0; j < 2; j++) {
            float4 f;
            if (valid)
                f = (w == 2) ? __ldcg(&src[g_part + 8 * j]) : __ldg(&src[g_part + 8 * j]);
            else
                f = make_float4(0.f, 0.f, 0.f, 0.f);
            cvt_sts(S, dstoff, r, g_half * 128 + (g_part + 8 * j) * 8, f);
        }
    }
}

// ---------------- register-resident fused 2-layer MLP ----------------
// Each warp: 16 rows, FULL 128n for layer 1; acc1 fragments repacked in
// registers as layer-2 A fragments (C-frag == A-frag layout identity).
// ONE __syncthreads per chunk (double-buffered A + sIdx).
__device__ __forceinline__ void run_mlp(
    char* S, uint32_t sb, int tid, int wid, int l,
    int w, int count, const int4* __restrict__ elist, float* __restrict__ scatp,
    const float* __restrict__ Ap, const float* __restrict__ Bp,
    const float* __restrict__ x, const float* __restrict__ eattr,
    int ctaoff, int cstride, float* __restrict__ nodeout)
{
    const int mbase = wid * 16;      // 16 rows per warp

    const uint32_t a_row  = (uint32_t)(mbase + (l & 15));
    const uint32_t a_cb16 = (uint32_t)((l >> 4) * 16);
    const uint32_t a_xor  = (a_row & 7u) << 4;
    const uint32_t a_lane = a_row * 256u;          // + buffer base per chunk

    const uint32_t b_rowoff = (uint32_t)(((l >> 4) << 3) + (l & 7));
    const uint32_t b_cb16   = ((uint32_t)(l >> 3) & 1u) * 16u;
    const uint32_t b_xor    = ((uint32_t)l & 7u) << 4;
    const uint32_t bW1 = sb + OFF_W1 + b_rowoff * 256u;
    const uint32_t bW2 = sb + OFF_W2 + b_rowoff * 256u;

    const int erow = (l >> 2);                       // 0..7
    const int ccol = (l & 3) * 2;

    // per-lane bias registers (full n for layer 1)
    float bias1[16][2], bias2[8][2];
    {
        const float* B1s = (const float*)(S + OFF_B1);
        const float* B2s = (const float*)(S + OFF_B2);
        #pragma unroll
        for (int nt = 0; nt < 16; nt++) {
            bias1[nt][0] = B1s[nt * 8 + ccol];
            bias1[nt][1] = B1s[nt * 8 + ccol + 1];
        }
        #pragma unroll
        for (int nt = 0; nt < 8; nt++) {
            bias2[nt][0] = B2s[nt * 8 + ccol];
            bias2[nt][1] = B2s[nt * 8 + ccol + 1];
        }
    }

    int nch = (count + 127) >> 7;
    if (ctaoff >= nch) return;   // uniform per CTA — safe with in-loop syncs

    // ---- prologue: gather first chunk into A0 ----
    gather_chunk(S, OFF_A0, OFF_IDX0, ctaoff << 7, count, w,
                 elist, Ap, Bp, x, eattr, wid, l);
    __syncthreads();

    int p = 0;
    for (int ch = ctaoff; ch < nch; ch += cstride, p ^= 1) {
        const uint32_t aCur = sb + (p ? OFF_A1 : OFF_A0) + a_lane;
        const uint32_t curIdx = p ? OFF_IDX1 : OFF_IDX0;

        // ---- issue next-chunk gather FIRST (LDG latency hides under MMAs) ----
        int nxt = ch + cstride;
        if (nxt < nch)
            gather_chunk(S, p ? OFF_A0 : OFF_A1, p ? OFF_IDX0 : OFF_IDX1,
                         nxt << 7, count, w, elist, Ap, Bp, x, eattr, wid, l);

        // ---- layer 1: 16m x 128n per warp, K=128 ----
        float acc1[16][4];
        #pragma unroll
        for (int nt = 0; nt < 16; nt++) {
            acc1[nt][0] = bias1[nt][0];
            acc1[nt][1] = bias1[nt][1];
            acc1[nt][2] = bias1[nt][0];
            acc1[nt][3] = bias1[nt][1];
        }
        #pragma unroll
        for (int kt = 0; kt < 8; kt++) {
            uint32_t ka = (uint32_t)(kt * 32);
            uint32_t af[4];
            LDMX4(af, aCur + ((ka + a_cb16) ^ a_xor));
            #pragma unroll
            for (int np = 0; np < 8; np++) {
                uint32_t bfr[4];
                LDMX4(bfr, bW1 + (uint32_t)(np * 4096) + ((ka + b_cb16) ^ b_xor));
                MMA16816(acc1[2*np],   af, bfr[0], bfr[1]);
                MMA16816(acc1[2*np+1], af, bfr[2], bfr[3]);
            }
        }

        // ---- relu + pack to halves IN REGISTERS (C-frag -> A-frag identity) ----
        uint32_t pk[16][2];
        #pragma unroll
        for (int nt = 0; nt < 16; nt++) {
            __half2 h01 = __floats2half2_rn(fmaxf(acc1[nt][0], 0.f), fmaxf(acc1[nt][1], 0.f));
            __half2 h23 = __floats2half2_rn(fmaxf(acc1[nt][2], 0.f), fmaxf(acc1[nt][3], 0.f));
            pk[nt][0] = *(uint32_t*)&h01;
            pk[nt][1] = *(uint32_t*)&h23;
        }

        // ---- layer 2: 16m x 64n per warp, K=128, A from registers ----
        float acc2[8][4];
        #pragma unroll
        for (int nt = 0; nt < 8; nt++) {
            acc2[nt][0] = bias2[nt][0];
            acc2[nt][1] = bias2[nt][1];
            acc2[nt][2] = bias2[nt][0];
            acc2[nt][3] = bias2[nt][1];
        }
        #pragma unroll
        for (int kt = 0; kt < 8; kt++) {
            uint32_t ka = (uint32_t)(kt * 32);
            #pragma unroll
            for (int np = 0; np < 4; np++) {
                uint32_t bfr[4];
                LDMX4(bfr, bW2 + (uint32_t)(np * 4096) + ((ka + b_cb16) ^ b_xor));
                MMA16816R(acc2[2*np],   pk[2*kt][0], pk[2*kt][1], pk[2*kt+1][0], pk[2*kt+1][1], bfr[0], bfr[1]);
                MMA16816R(acc2[2*np+1], pk[2*kt][0], pk[2*kt][1], pk[2*kt+1][0], pk[2*kt+1][1], bfr[2], bfr[3]);
            }
        }

        // ---- epilogue: relu + shuffle-pair into float4 + scatter ----
        {
            int* sIdx = (int*)(S + curIdx);
            int r0 = mbase + erow;
            int myrow = r0 + ((l & 1) << 3);
            int node = sIdx[myrow];
            const int csel = 4 * ((l >> 1) & 1);
            #pragma unroll
            for (int nt = 0; nt < 8; nt++) {
                float v0 = fmaxf(acc2[nt][0], 0.f);
                float v1 = fmaxf(acc2[nt][1], 0.f);
                float v2 = fmaxf(acc2[nt][2], 0.f);
                float v3 = fmaxf(acc2[nt][3], 0.f);
                float s0 = __shfl_xor_sync(0xffffffffu, v0, 1);
                float s1 = __shfl_xor_sync(0xffffffffu, v1, 1);
                float s2 = __shfl_xor_sync(0xffffffffu, v2, 1);
                float s3 = __shfl_xor_sync(0xffffffffu, v3, 1);
                float4 q = (l & 1) ? make_float4(s2, s3, v2, v3)
                                   : make_float4(v0, v1, s0, s1);
                if (node >= 0) {
                    int col = nt * 8 + csel;
                    if (w < 2)
                        atomicAdd((float4*)(scatp + (size_t)node * 64 + col), q);
                    else
                        *(float4*)(nodeout + (size_t)node * 64 + col) = q;
                }
            }
        }
        __syncthreads();   // A[p^1]/sIdx[p^1] ready; A[p]/sIdx[p] consumed
    }
}

// ---------------- single persistent kernel ----------------
__global__ void __launch_bounds__(256, 1)
fused_kernel(int nN, int nE,
             const float* __restrict__ x, const void* __restrict__ eidx,
             const float* __restrict__ eattr,
             const float* __restrict__ Wo1, const float* __restrict__ bo1,
             const float* __restrict__ Wo2, const float* __restrict__ bo2,
             const float* __restrict__ Wi1, const float* __restrict__ bi1,
             const float* __restrict__ Wi2, const float* __restrict__ bi2,
             const float* __restrict__ Wn1, const float* __restrict__ bn1,
             const float* __restrict__ Wn2, const float* __restrict__ bn2,
             float* __restrict__ nodeout)
{
    extern __shared__ __align__(256) char smem[];
    char* S = smem;
    const uint32_t sb = smem_u32(smem);
    const int tid = threadIdx.x;
    const int wid = tid >> 5;
    const int l = tid & 31;
    const long long* p64 = (const long long*)eidx;
    const int* p32 = (const int*)eidx;

    // per-CTA index-dtype detection
    __shared__ int s_is64;
    if (tid == 0) {
        const int* wds = (const int*)eidx;
        int nz = 0;
        #pragma unroll
        for (int k = 0; k < 32; k++) nz |= wds[2 * k + 1];
        s_is64 = (nz == 0) ? 1 : 0;
    }

    // edge-direction for this CTA; stage edge weights (overlaps phase 0)
    const int w = blockIdx.x & 1;
    stage_weights(S, tid,
                  w ? Wi1 : Wo1, w ? bi1 : bo1,
                  w ? Wi2 : Wo2, w ? bi2 : bo2);
    __syncthreads();
    const int is64 = s_is64;

    // ---- phase 0: zero flows + compaction into packed int4 records ----
    {
        int stride = gridDim.x * 256;
        for (int e0 = blockIdx.x * 256 + wid * 32; e0 < nE; e0 += stride) {
            int e = e0 + l;
            bool is_out = false, is_in = false;
            int r = 0, c = 0;
            if (e < nE) {
                if (is64) { r = (int)p64[e]; c = (int)p64[nE + e]; }
                else      { r = p32[e];      c = p32[nE + e]; }
                is_out = (r < c);
                is_in  = (r > c);
            }
            unsigned mo = __ballot_sync(0xffffffffu, is_out);
            unsigned mi = __ballot_sync(0xffffffffu, is_in);
            int bo = 0, bi = 0;
            if (l == 0) {
                if (mo) bo = atomicAdd(&g_counts[0], __popc(mo));
                if (mi) bi = atomicAdd(&g_counts[1], __popc(mi));
            }
            bo = __shfl_sync(0xffffffffu, bo, 0);
            bi = __shfl_sync(0xffffffffu, bi, 0);
            unsigned lt = (1u << l) - 1u;
            if (is_out) g_elist0[bo + __popc(mo & lt)] = make_int4(e, c, r, 0);
            if (is_in)  g_elist1[bi + __popc(mi & lt)] = make_int4(e, c, r, 0);
        }
        int total = nN * 16;
        float4 z = make_float4(0.f, 0.f, 0.f, 0.f);
        for (int i = blockIdx.x * 256 + tid; i < total; i += gridDim.x * 256) {
            ((float4*)g_flow_in)[i]  = z;
            ((float4*)g_flow_out)[i] = z;
        }
    }
    grid_barrier(0);

    // ---- phase 1: edge MLPs (even CTAs: out-list, odd CTAs: in-list) ----
    {
        int count = g_counts[w];
        const int4* elist = w ? g_elist1 : g_elist0;
        float* scatp = w ? g_flow_in : g_flow_out;
        run_mlp(S, sb, tid, wid, l, w, count, elist, scatp,
                nullptr, nullptr, x, eattr,
                blockIdx.x >> 1, gridDim.x >> 1, nullptr);
    }
    grid_barrier(1);

    // ---- phase 2: node MLP ----
    stage_weights(S, tid, Wn1, bn1, Wn2, bn2);
    __syncthreads();
    run_mlp(S, sb, tid, wid, l, 2, nN, nullptr, nullptr,
            g_flow_in, g_flow_out, x, eattr,
            blockIdx.x, gridDim.x, nodeout);

    // restore g_counts = 0 for the next launch (contract)
    if (blockIdx.x == 0 && tid == 0) {
        g_counts[0] = 0;
        g_counts[1] = 0;
    }
}

// ---------------- launch ----------------
extern "C" void kernel_launch(void* const* d_in, const int* in_sizes, int n_in,
                              void* d_out, int out_size) {
    const float* x     = (const float*)d_in[0];
    const void*  eidx  = d_in[1];
    const float* eattr = (const float*)d_in[2];
    const float* Wo1 = (const float*)d_in[3];
    const float* bo1 = (const float*)d_in[4];
    const float* Wo2 = (const float*)d_in[5];
    const float* bo2 = (const float*)d_in[6];
    const float* Wi1 = (const float*)d_in[7];
    const float* bi1 = (const float*)d_in[8];
    const float* Wi2 = (const float*)d_in[9];
    const float* bi2 = (const float*)d_in[10];
    const float* Wn1 = (const float*)d_in[11];
    const float* bn1 = (const float*)d_in[12];
    const float* Wn2 = (const float*)d_in[13];
    const float* bn2 = (const float*)d_in[14];

    int nN = in_sizes[0] / 64;
    int nE = in_sizes[2] / 64;

    cudaFuncSetAttribute(fused_kernel, cudaFuncAttributeMaxDynamicSharedMemorySize, SMEM_TOTAL);

    fused_kernel<<<GRID, 256, SMEM_TOTAL>>>(nN, nE, x, eidx, eattr,
                                            Wo1, bo1, Wo2, bo2,
                                            Wi1, bi1, Wi2, bi2,
                                            Wn1, bn1, Wn2, bn2,
                                            (float*)d_out);
}